// round 7
// baseline (speedup 1.0000x reference)
#include <cuda_runtime.h>
#include <math.h>

#define B 32
#define HH 512
#define WW 512
#define NPIX (HH*WW)          // 262144
#define NTOT (B*NPIX)         // 8388608
#define KRAD 15               // box radius

// swizzle: one pad float per 16 -> stride-16 access patterns become
// stride-17 (odd) -> conflict-free across 32 banks
#define SWZ(i) ((i) + ((i) >> 4))
#define SWW 544                // 512 + 32 pad floats per row

// Scratch: horizontal box sums of y_target. 33.5 MB.
__device__ float g_Hsum[NTOT];

// Accumulators (zero at module load; Pass-B tail restores zeros every call)
__device__ float g_sum_t[B];
__device__ float g_sum_p[B];
__device__ float g_wsum[B];
__device__ float g_inter[B];
__device__ float g_uni[B];
__device__ float g_qsum[B];
__device__ float g_bce;
__device__ int   g_done;

__device__ __forceinline__ float fsigmoid(float x) {
    return __fdividef(1.f, 1.f + __expf(-x));
}

// -------- Pass A: horizontal box sums + per-image sum_t, sum_p, global bce ---
// 8 warps per block, one warp per row. 2048 blocks cover 16384 rows.
__global__ __launch_bounds__(256) void k_passA(const float* __restrict__ P,
                                               const float* __restrict__ T) {
    __shared__ float sIn[8][SWW];    // swizzled; reused as output staging
    __shared__ float red[3][8];

    const int warp = threadIdx.x >> 5;
    const int lane = threadIdx.x & 31;
    const int rowg = blockIdx.x * 8 + warp;          // global row 0..16383
    const int b    = blockIdx.x >> 6;                // 64 blocks per image

    const float4* t4 = (const float4*)(T + (size_t)rowg * WW);
    const float4* p4 = (const float4*)(P + (size_t)rowg * WW);

    float lsum_t = 0.f, lsum_p = 0.f, lbce = 0.f;
    #pragma unroll
    for (int i = 0; i < 4; i++) {
        float4 tv = __ldcs(&t4[lane + 32*i]);    // streaming: don't pollute L2
        float4 pv = __ldcs(&p4[lane + 32*i]);
        const int c0 = 4*lane + 128*i;
        sIn[warp][SWZ(c0+0)] = tv.x;
        sIn[warp][SWZ(c0+1)] = tv.y;
        sIn[warp][SWZ(c0+2)] = tv.z;
        sIn[warp][SWZ(c0+3)] = tv.w;
        float ts[4] = {tv.x, tv.y, tv.z, tv.w};
        float xs[4] = {pv.x, pv.y, pv.z, pv.w};
        #pragma unroll
        for (int k = 0; k < 4; k++) {
            float t = ts[k], x = xs[k];
            float p = fsigmoid(x);
            lsum_t += t;
            lsum_p += p;
            float sabs = (x >= 0.f) ? p : (1.f - p);
            lbce += fmaxf(x, 0.f) - x * t - __logf(sabs);
        }
    }
    __syncwarp();

    // per-lane sliding window over 16 contiguous columns, conflict-free reads
    const int base = lane * 16;
    float h[16];
    float s = 0.f;
    #pragma unroll
    for (int kk = 0; kk < 31; kk++) {
        int k = base - KRAD + kk;
        if (k >= 0 && k < WW) s += sIn[warp][SWZ(k)];
    }
    h[0] = s;
    #pragma unroll
    for (int j = 1; j < 16; j++) {
        int ka = base + KRAD + j;
        int kr = base - KRAD - 1 + j;
        if (ka < WW) s += sIn[warp][SWZ(ka)];
        if (kr >= 0) s -= sIn[warp][SWZ(kr)];
        h[j] = s;
    }
    __syncwarp();

    #pragma unroll
    for (int j = 0; j < 16; j++)
        sIn[warp][SWZ(base + j)] = h[j];
    __syncwarp();

    float4* h4 = (float4*)(g_Hsum + (size_t)rowg * WW);
    #pragma unroll
    for (int i = 0; i < 4; i++) {
        const int c0 = 4*lane + 128*i;
        float4 o;
        o.x = sIn[warp][SWZ(c0+0)];
        o.y = sIn[warp][SWZ(c0+1)];
        o.z = sIn[warp][SWZ(c0+2)];
        o.w = sIn[warp][SWZ(c0+3)];
        h4[lane + 32*i] = o;     // default policy: keep H in L2 for Pass B
    }

    #pragma unroll
    for (int o = 16; o > 0; o >>= 1) {
        lsum_t += __shfl_xor_sync(~0u, lsum_t, o);
        lsum_p += __shfl_xor_sync(~0u, lsum_p, o);
        lbce   += __shfl_xor_sync(~0u, lbce,   o);
    }
    if (lane == 0) { red[0][warp] = lsum_t; red[1][warp] = lsum_p; red[2][warp] = lbce; }
    __syncthreads();
    if (threadIdx.x == 0) {
        float a = 0.f, c = 0.f, d = 0.f;
        #pragma unroll
        for (int w = 0; w < 8; w++) { a += red[0][w]; c += red[1][w]; d += red[2][w]; }
        atomicAdd(&g_sum_t[b], a);
        atomicAdd(&g_sum_p[b], c);
        atomicAdd(&g_bce, d);
    }
}

// -------- Pass B: vertical box via diff-decomposition + weighted sums + E ----
// grid 2048: b = bx>>6, band = (bx>>2)&15 (32 rows), strip = bx&3 (128 cols).
// smem holds only the 31 difference rows d[i] = H[r0+16+i] - H[r0-15+i]
// (15.5 KB); vsum0 comes from 31 independent global loads. 9 blocks/SM target.
__global__ __launch_bounds__(128, 9) void k_passB(const float* __restrict__ P,
                                                  const float* __restrict__ T,
                                                  float* __restrict__ out) {
    __shared__ __align__(16) float sD[31][128];    // 15.5 KB
    __shared__ float red[4][4];
    __shared__ int s_last;

    const int bx    = blockIdx.x;
    const int b     = bx >> 6;
    const int band  = (bx >> 2) & 15;
    const int strip = bx & 3;
    const int tid   = threadIdx.x;
    const int warp  = tid >> 5, lane = tid & 31;
    const int gcol  = strip * 128 + tid;
    const int r0    = band * 32;

    const float* Hb = g_Hsum + (size_t)b * NPIX;
    const float* Tb = T + (size_t)b * NPIX + gcol;
    const float* Pb = P + (size_t)b * NPIX + gcol;

    // Stage 31 diff rows: per warp 8 rows, each = (float4 a) - (float4 b).
    const float4 z4 = make_float4(0.f, 0.f, 0.f, 0.f);
    #pragma unroll
    for (int j = warp; j < 31; j += 4) {
        int ra = r0 + 16 + j;              // r0+16 .. r0+46
        int rr = r0 - 15 + j;              // r0-15 .. r0+15
        float4 a = (ra < HH) ? ((const float4*)(Hb + (size_t)ra * WW + strip * 128))[lane] : z4;
        float4 c = (rr >= 0) ? ((const float4*)(Hb + (size_t)rr * WW + strip * 128))[lane] : z4;
        float4 d; d.x = a.x - c.x; d.y = a.y - c.y; d.z = a.z - c.z; d.w = a.w - c.w;
        ((float4*)sD[j])[lane] = d;
    }

    // vsum0 = sum of H rows r0-15 .. r0+15 at gcol (31 independent loads,
    // 4 interleaved partial sums -> short dependency chains)
    float acc0 = 0.f, acc1 = 0.f, acc2 = 0.f, acc3 = 0.f;
    #pragma unroll
    for (int j = 0; j < 31; j++) {
        int gr = r0 - KRAD + j;
        float v = (gr >= 0 && gr < HH) ? Hb[(size_t)gr * WW + gcol] : 0.f;
        if ((j & 3) == 0) acc0 += v;
        else if ((j & 3) == 1) acc1 += v;
        else if ((j & 3) == 2) acc2 += v;
        else acc3 += v;
    }
    float vsum = (acc0 + acc1) + (acc2 + acc3);
    __syncthreads();

    const float mean_p = g_sum_p[b] * (1.f / (float)NPIX);
    const float mean_t = g_sum_t[b] * (1.f / (float)NPIX);

    float a_w = 0.f, a_i = 0.f, a_u = 0.f, a_q = 0.f;
    #pragma unroll 8
    for (int i = 0; i < 32; i++) {
        float box = vsum * (1.f / 961.f);
        float t = __ldcs(Tb + (size_t)(r0 + i) * WW);   // streaming reads
        float x = __ldcs(Pb + (size_t)(r0 + i) * WW);
        float p = fsigmoid(x);
        float w = 1.f + 5.f * fabsf(box - t);
        a_w += w;
        a_i += p * t * w;
        a_u += (p + t) * w;
        float fp = p - mean_p;
        float ft = t - mean_t;
        float efm = __fdividef(2.f * fp * ft + 1e-8f, fp * fp + ft * ft + 1e-8f);
        float q = 1.f + efm;
        a_q += q * q * 0.25f;
        if (i < 31) vsum += sD[i][tid];
    }

    #pragma unroll
    for (int o = 16; o > 0; o >>= 1) {
        a_w += __shfl_xor_sync(~0u, a_w, o);
        a_i += __shfl_xor_sync(~0u, a_i, o);
        a_u += __shfl_xor_sync(~0u, a_u, o);
        a_q += __shfl_xor_sync(~0u, a_q, o);
    }
    if (lane == 0) { red[0][warp] = a_w; red[1][warp] = a_i; red[2][warp] = a_u; red[3][warp] = a_q; }
    __syncthreads();
    if (tid == 0) {
        float rw = 0.f, ri = 0.f, ru = 0.f, rq = 0.f;
        #pragma unroll
        for (int w = 0; w < 4; w++) { rw += red[0][w]; ri += red[1][w]; ru += red[2][w]; rq += red[3][w]; }
        atomicAdd(&g_wsum[b],  rw);
        atomicAdd(&g_inter[b], ri);
        atomicAdd(&g_uni[b],   ru);
        atomicAdd(&g_qsum[b],  rq);
        __threadfence();
        s_last = (atomicAdd(&g_done, 1) == gridDim.x - 1);
    }
    __syncthreads();

    if (s_last) {
        const int ib = tid;   // threads 0..31 handle one image each
        float v = 0.f;
        if (ib < B) {
            float bce = atomicAdd(&g_bce, 0.f) * (1.f / (float)NTOT);
            float ws  = atomicAdd(&g_wsum[ib],  0.f);
            float in_ = atomicAdd(&g_inter[ib], 0.f);
            float un_ = atomicAdd(&g_uni[ib],   0.f);
            float qs  = atomicAdd(&g_qsum[ib],  0.f);
            float wbce = (ws * bce + 1e-8f) / (ws + 1e-8f);
            float wiou = 1.f - (in_ + 1.f + 1e-8f) / (un_ - in_ + 1.f + 1e-8f);
            float el   = 1.f - qs * (1.f / (float)NPIX);
            v = wbce + wiou + el;
        }
        #pragma unroll
        for (int o = 16; o > 0; o >>= 1) v += __shfl_xor_sync(~0u, v, o);
        if (ib == 0) out[0] = v * (1.f / (float)B);
        if (ib < B) {
            g_sum_t[ib] = 0.f; g_sum_p[ib] = 0.f;
            g_wsum[ib]  = 0.f; g_inter[ib] = 0.f;
            g_uni[ib]   = 0.f; g_qsum[ib]  = 0.f;
        }
        if (ib == 0) { g_bce = 0.f; g_done = 0; }
    }
}

extern "C" void kernel_launch(void* const* d_in, const int* in_sizes, int n_in,
                              void* d_out, int out_size) {
    const float* y_pred   = (const float*)d_in[0];
    const float* y_target = (const float*)d_in[1];
    float* out = (float*)d_out;

    k_passA<<<2048, 256>>>(y_pred, y_target);
    k_passB<<<2048, 128>>>(y_pred, y_target, out);
}

// round 8
// speedup vs baseline: 1.3315x; 1.3315x over previous
#include <cuda_runtime.h>
#include <math.h>

#define B 32
#define HH 512
#define WW 512
#define NPIX (HH*WW)          // 262144
#define NTOT (B*NPIX)         // 8388608
#define KRAD 15               // box radius

// swizzle: one pad float per 16 -> stride-16 access patterns become
// stride-17 (odd) -> conflict-free across 32 banks
#define SWZ(i) ((i) + ((i) >> 4))
#define SWW 544                // 512 + 32 pad floats per row

// Scratch: horizontal box sums of y_target. 33.5 MB.
__device__ float g_Hsum[NTOT];

// Accumulators (zero at module load; Pass-B tail restores zeros every call)
__device__ float g_sum_t[B];
__device__ float g_sum_p[B];
__device__ float g_wsum[B];
__device__ float g_inter[B];
__device__ float g_uni[B];
__device__ float g_qsum[B];
__device__ float g_bce;
__device__ int   g_done;

__device__ __forceinline__ float fsigmoid(float x) {
    return __fdividef(1.f, 1.f + __expf(-x));
}

// -------- Pass A: horizontal box sums + per-image sum_t, sum_p, global bce ---
// 8 warps per block, one warp per row. 2048 blocks cover 16384 rows.
// All loads default policy: T/P/H must stay L2-resident for Pass B.
__global__ __launch_bounds__(256) void k_passA(const float* __restrict__ P,
                                               const float* __restrict__ T) {
    __shared__ float sIn[8][SWW];    // swizzled; reused as output staging
    __shared__ float red[3][8];

    const int warp = threadIdx.x >> 5;
    const int lane = threadIdx.x & 31;
    const int rowg = blockIdx.x * 8 + warp;          // global row 0..16383
    const int b    = blockIdx.x >> 6;                // 64 blocks per image

    const float4* t4 = (const float4*)(T + (size_t)rowg * WW);
    const float4* p4 = (const float4*)(P + (size_t)rowg * WW);

    float lsum_t = 0.f, lsum_p = 0.f, lbce = 0.f;
    #pragma unroll
    for (int i = 0; i < 4; i++) {
        float4 tv = t4[lane + 32*i];
        float4 pv = p4[lane + 32*i];
        const int c0 = 4*lane + 128*i;
        sIn[warp][SWZ(c0+0)] = tv.x;
        sIn[warp][SWZ(c0+1)] = tv.y;
        sIn[warp][SWZ(c0+2)] = tv.z;
        sIn[warp][SWZ(c0+3)] = tv.w;
        float ts[4] = {tv.x, tv.y, tv.z, tv.w};
        float xs[4] = {pv.x, pv.y, pv.z, pv.w};
        #pragma unroll
        for (int k = 0; k < 4; k++) {
            float t = ts[k], x = xs[k];
            float p = fsigmoid(x);
            lsum_t += t;
            lsum_p += p;
            float sabs = (x >= 0.f) ? p : (1.f - p);
            lbce += fmaxf(x, 0.f) - x * t - __logf(sabs);
        }
    }
    __syncwarp();

    // per-lane sliding window over 16 contiguous columns, conflict-free reads
    const int base = lane * 16;
    float h[16];
    float s = 0.f;
    #pragma unroll
    for (int kk = 0; kk < 31; kk++) {
        int k = base - KRAD + kk;
        if (k >= 0 && k < WW) s += sIn[warp][SWZ(k)];
    }
    h[0] = s;
    #pragma unroll
    for (int j = 1; j < 16; j++) {
        int ka = base + KRAD + j;
        int kr = base - KRAD - 1 + j;
        if (ka < WW) s += sIn[warp][SWZ(ka)];
        if (kr >= 0) s -= sIn[warp][SWZ(kr)];
        h[j] = s;
    }
    __syncwarp();

    #pragma unroll
    for (int j = 0; j < 16; j++)
        sIn[warp][SWZ(base + j)] = h[j];
    __syncwarp();

    float4* h4 = (float4*)(g_Hsum + (size_t)rowg * WW);
    #pragma unroll
    for (int i = 0; i < 4; i++) {
        const int c0 = 4*lane + 128*i;
        float4 o;
        o.x = sIn[warp][SWZ(c0+0)];
        o.y = sIn[warp][SWZ(c0+1)];
        o.z = sIn[warp][SWZ(c0+2)];
        o.w = sIn[warp][SWZ(c0+3)];
        h4[lane + 32*i] = o;
    }

    #pragma unroll
    for (int o = 16; o > 0; o >>= 1) {
        lsum_t += __shfl_xor_sync(~0u, lsum_t, o);
        lsum_p += __shfl_xor_sync(~0u, lsum_p, o);
        lbce   += __shfl_xor_sync(~0u, lbce,   o);
    }
    if (lane == 0) { red[0][warp] = lsum_t; red[1][warp] = lsum_p; red[2][warp] = lbce; }
    __syncthreads();
    if (threadIdx.x == 0) {
        float a = 0.f, c = 0.f, d = 0.f;
        #pragma unroll
        for (int w = 0; w < 8; w++) { a += red[0][w]; c += red[1][w]; d += red[2][w]; }
        atomicAdd(&g_sum_t[b], a);
        atomicAdd(&g_sum_p[b], c);
        atomicAdd(&g_bce, d);
    }
}

// -------- Pass B: vertical box via SMEM-staged halo + weighted sums + E ------
// grid 4096: b = bx>>7, band = (bx>>2)&31 (16 rows), strip = bx&3 (128 cols).
// 46-row halo = 23.5 KB smem -> 9 blocks/SM (36 warps). Default loads: the
// full working set (T+P+H = 100.5 MB) fits L2.
__global__ __launch_bounds__(128, 9) void k_passB(const float* __restrict__ P,
                                                  const float* __restrict__ T,
                                                  float* __restrict__ out) {
    __shared__ __align__(16) float sH[46][128];    // 23.5 KB
    __shared__ float red[4][4];
    __shared__ int s_last;

    const int bx    = blockIdx.x;
    const int b     = bx >> 7;
    const int band  = (bx >> 2) & 31;
    const int strip = bx & 3;
    const int tid   = threadIdx.x;
    const int warp  = tid >> 5, lane = tid & 31;
    const int gcol  = strip * 128 + tid;
    const int r0    = band * 16;

    const float* Hb = g_Hsum + (size_t)b * NPIX;
    const float* Tb = T + (size_t)b * NPIX;
    const float* Pb = P + (size_t)b * NPIX;

    // Stage H rows [r0-15, r0+30] for this strip: independent float4 loads.
    #pragma unroll
    for (int j = warp; j < 46; j += 4) {
        int gr = r0 - KRAD + j;
        float4 v = make_float4(0.f, 0.f, 0.f, 0.f);
        if (gr >= 0 && gr < HH)
            v = ((const float4*)(Hb + (size_t)gr * WW + strip * 128))[lane];
        ((float4*)sH[j])[lane] = v;
    }
    __syncthreads();

    const float mean_p = g_sum_p[b] * (1.f / (float)NPIX);
    const float mean_t = g_sum_t[b] * (1.f / (float)NPIX);

    // init vertical window: smem rows 0..30 (global r0-15..r0+15)
    float vsum = 0.f;
    #pragma unroll
    for (int j = 0; j < 31; j++) vsum += sH[j][tid];

    float a_w = 0.f, a_i = 0.f, a_u = 0.f, a_q = 0.f;
    #pragma unroll
    for (int i = 0; i < 16; i++) {
        float box = vsum * (1.f / 961.f);
        float t = Tb[(size_t)(r0 + i) * WW + gcol];
        float x = Pb[(size_t)(r0 + i) * WW + gcol];
        float p = fsigmoid(x);
        float w = 1.f + 5.f * fabsf(box - t);
        a_w += w;
        a_i += p * t * w;
        a_u += (p + t) * w;
        float fp = p - mean_p;
        float ft = t - mean_t;
        float efm = __fdividef(2.f * fp * ft + 1e-8f, fp * fp + ft * ft + 1e-8f);
        float q = 1.f + efm;
        a_q += q * q * 0.25f;
        if (i < 15) vsum += sH[i + 31][tid] - sH[i][tid];
    }

    #pragma unroll
    for (int o = 16; o > 0; o >>= 1) {
        a_w += __shfl_xor_sync(~0u, a_w, o);
        a_i += __shfl_xor_sync(~0u, a_i, o);
        a_u += __shfl_xor_sync(~0u, a_u, o);
        a_q += __shfl_xor_sync(~0u, a_q, o);
    }
    if (lane == 0) { red[0][warp] = a_w; red[1][warp] = a_i; red[2][warp] = a_u; red[3][warp] = a_q; }
    __syncthreads();
    if (tid == 0) {
        float rw = 0.f, ri = 0.f, ru = 0.f, rq = 0.f;
        #pragma unroll
        for (int w = 0; w < 4; w++) { rw += red[0][w]; ri += red[1][w]; ru += red[2][w]; rq += red[3][w]; }
        atomicAdd(&g_wsum[b],  rw);
        atomicAdd(&g_inter[b], ri);
        atomicAdd(&g_uni[b],   ru);
        atomicAdd(&g_qsum[b],  rq);
        __threadfence();
        s_last = (atomicAdd(&g_done, 1) == gridDim.x - 1);
    }
    __syncthreads();

    if (s_last) {
        const int ib = tid;   // threads 0..31 handle one image each
        float v = 0.f;
        if (ib < B) {
            float bce = atomicAdd(&g_bce, 0.f) * (1.f / (float)NTOT);
            float ws  = atomicAdd(&g_wsum[ib],  0.f);
            float in_ = atomicAdd(&g_inter[ib], 0.f);
            float un_ = atomicAdd(&g_uni[ib],   0.f);
            float qs  = atomicAdd(&g_qsum[ib],  0.f);
            float wbce = (ws * bce + 1e-8f) / (ws + 1e-8f);
            float wiou = 1.f - (in_ + 1.f + 1e-8f) / (un_ - in_ + 1.f + 1e-8f);
            float el   = 1.f - qs * (1.f / (float)NPIX);
            v = wbce + wiou + el;
        }
        #pragma unroll
        for (int o = 16; o > 0; o >>= 1) v += __shfl_xor_sync(~0u, v, o);
        if (ib == 0) out[0] = v * (1.f / (float)B);
        if (ib < B) {
            g_sum_t[ib] = 0.f; g_sum_p[ib] = 0.f;
            g_wsum[ib]  = 0.f; g_inter[ib] = 0.f;
            g_uni[ib]   = 0.f; g_qsum[ib]  = 0.f;
        }
        if (ib == 0) { g_bce = 0.f; g_done = 0; }
    }
}

extern "C" void kernel_launch(void* const* d_in, const int* in_sizes, int n_in,
                              void* d_out, int out_size) {
    const float* y_pred   = (const float*)d_in[0];
    const float* y_target = (const float*)d_in[1];
    float* out = (float*)d_out;

    k_passA<<<2048, 256>>>(y_pred, y_target);
    k_passB<<<4096, 128>>>(y_pred, y_target, out);
}

// round 10
// speedup vs baseline: 1.6117x; 1.2104x over previous
#include <cuda_runtime.h>
#include <cuda_bf16.h>
#include <math.h>

#define B 32
#define HH 512
#define WW 512
#define NPIX (HH*WW)          // 262144
#define NTOT (B*NPIX)         // 8388608
#define KRAD 15               // box radius

// swizzle: one pad float per 16 -> stride-16 access patterns become
// stride-17 (odd) -> conflict-free across 32 banks
#define SWZ(i) ((i) + ((i) >> 4))
#define SWW 544                // 512 + 32 pad floats per row

// Scratch: horizontal box sums of y_target, bf16. 16.75 MB.
// (H in [0,31]; bf16 error ~3e-4 on box -> ~1e-4 on final scalar, gate is 1e-3)
__device__ __nv_bfloat16 g_Hb[NTOT];

// Accumulators (zero at module load; Pass-B tail restores zeros every call)
__device__ float g_sum_t[B];
__device__ float g_sum_p[B];
__device__ float g_wsum[B];
__device__ float g_inter[B];
__device__ float g_uni[B];
__device__ float g_qsum[B];
__device__ float g_bce;
__device__ int   g_done;

__device__ __forceinline__ float fsigmoid(float x) {
    return __fdividef(1.f, 1.f + __expf(-x));
}

// -------- Pass A: horizontal box sums (bf16 out) + sum_t, sum_p, bce ---------
// 8 warps per block, one warp per row. 2048 blocks cover 16384 rows.
__global__ __launch_bounds__(256) void k_passA(const float* __restrict__ P,
                                               const float* __restrict__ T) {
    __shared__ float sIn[8][SWW];    // swizzled input staging
    __shared__ float red[3][8];

    const int warp = threadIdx.x >> 5;
    const int lane = threadIdx.x & 31;
    const int rowg = blockIdx.x * 8 + warp;          // global row 0..16383
    const int b    = blockIdx.x >> 6;                // 64 blocks per image

    const float4* t4 = (const float4*)(T + (size_t)rowg * WW);
    const float4* p4 = (const float4*)(P + (size_t)rowg * WW);

    float lsum_t = 0.f, lsum_p = 0.f, lbce = 0.f;
    #pragma unroll
    for (int i = 0; i < 4; i++) {
        float4 tv = t4[lane + 32*i];
        float4 pv = p4[lane + 32*i];
        const int c0 = 4*lane + 128*i;
        sIn[warp][SWZ(c0+0)] = tv.x;
        sIn[warp][SWZ(c0+1)] = tv.y;
        sIn[warp][SWZ(c0+2)] = tv.z;
        sIn[warp][SWZ(c0+3)] = tv.w;
        float ts[4] = {tv.x, tv.y, tv.z, tv.w};
        float xs[4] = {pv.x, pv.y, pv.z, pv.w};
        #pragma unroll
        for (int k = 0; k < 4; k++) {
            float t = ts[k], x = xs[k];
            float p = fsigmoid(x);
            lsum_t += t;
            lsum_p += p;
            float sabs = (x >= 0.f) ? p : (1.f - p);
            lbce += fmaxf(x, 0.f) - x * t - __logf(sabs);
        }
    }
    __syncwarp();

    // per-lane sliding window over 16 contiguous columns, conflict-free reads
    const int base = lane * 16;
    float h[16];
    float s = 0.f;
    #pragma unroll
    for (int kk = 0; kk < 31; kk++) {
        int k = base - KRAD + kk;
        if (k >= 0 && k < WW) s += sIn[warp][SWZ(k)];
    }
    h[0] = s;
    #pragma unroll
    for (int j = 1; j < 16; j++) {
        int ka = base + KRAD + j;
        int kr = base - KRAD - 1 + j;
        if (ka < WW) s += sIn[warp][SWZ(ka)];
        if (kr >= 0) s -= sIn[warp][SWZ(kr)];
        h[j] = s;
    }

    // pack 16 fp32 -> 16 bf16 (32B) and store coalesced (lane-contiguous)
    __align__(16) __nv_bfloat162 hb2[8];
    #pragma unroll
    for (int k = 0; k < 8; k++)
        hb2[k] = __floats2bfloat162_rn(h[2*k], h[2*k+1]);
    uint4* dst = (uint4*)(g_Hb + (size_t)rowg * WW + base);
    const uint4* src = (const uint4*)hb2;
    dst[0] = src[0];
    dst[1] = src[1];

    #pragma unroll
    for (int o = 16; o > 0; o >>= 1) {
        lsum_t += __shfl_xor_sync(~0u, lsum_t, o);
        lsum_p += __shfl_xor_sync(~0u, lsum_p, o);
        lbce   += __shfl_xor_sync(~0u, lbce,   o);
    }
    if (lane == 0) { red[0][warp] = lsum_t; red[1][warp] = lsum_p; red[2][warp] = lbce; }
    __syncthreads();
    if (threadIdx.x == 0) {
        float a = 0.f, c = 0.f, d = 0.f;
        #pragma unroll
        for (int w = 0; w < 8; w++) { a += red[0][w]; c += red[1][w]; d += red[2][w]; }
        atomicAdd(&g_sum_t[b], a);
        atomicAdd(&g_sum_p[b], c);
        atomicAdd(&g_bce, d);
    }
}

// -------- Pass B: vertical box via SMEM halo (bf16->fp32) + sums + E ---------
// grid 2048, REVERSED decode (read most-recently-written data first -> L2 LRU
// alignment): bxr = 2047-bx; b = bxr>>6, band = (bxr>>2)&15 (32 rows),
// strip = bxr&3 (128 cols). Halo 62 rows fp32 = 31.75 KB smem.
__global__ __launch_bounds__(128, 9) void k_passB(const float* __restrict__ P,
                                                  const float* __restrict__ T,
                                                  float* __restrict__ out) {
    __shared__ __align__(16) float sH[62][128];    // 31.75 KB
    __shared__ float red[4][4];
    __shared__ int s_last;

    const int bxr   = 2047 - blockIdx.x;
    const int b     = bxr >> 6;
    const int band  = (bxr >> 2) & 15;
    const int strip = bxr & 3;
    const int tid   = threadIdx.x;
    const int warp  = tid >> 5, lane = tid & 31;
    const int gcol  = strip * 128 + tid;
    const int r0    = band * 32;

    const __nv_bfloat16* Hb = g_Hb + (size_t)b * NPIX;
    const float* Tb = T + (size_t)b * NPIX;
    const float* Pb = P + (size_t)b * NPIX;

    // Stage H rows [r0-15, r0+46]: each lane loads 4 bf16 (8B), converts to
    // fp32 once. Independent loads -> high MLP.
    #pragma unroll
    for (int j = warp; j < 62; j += 4) {
        int gr = r0 - KRAD + j;
        uint2 u = make_uint2(0u, 0u);
        if (gr >= 0 && gr < HH)
            u = ((const uint2*)(Hb + (size_t)gr * WW + strip * 128))[lane];
        float2 f0 = __bfloat1622float2(*(const __nv_bfloat162*)&u.x);
        float2 f1 = __bfloat1622float2(*(const __nv_bfloat162*)&u.y);
        ((float4*)sH[j])[lane] = make_float4(f0.x, f0.y, f1.x, f1.y);
    }
    __syncthreads();

    const float mean_p = g_sum_p[b] * (1.f / (float)NPIX);
    const float mean_t = g_sum_t[b] * (1.f / (float)NPIX);

    // init vertical window: smem rows 0..30 (global r0-15..r0+15)
    float vsum = 0.f;
    #pragma unroll
    for (int j = 0; j < 31; j++) vsum += sH[j][tid];

    float a_w = 0.f, a_i = 0.f, a_u = 0.f, a_q = 0.f;
    #pragma unroll 8
    for (int i = 0; i < 32; i++) {
        float box = vsum * (1.f / 961.f);
        float t = Tb[(size_t)(r0 + i) * WW + gcol];
        float x = Pb[(size_t)(r0 + i) * WW + gcol];
        float p = fsigmoid(x);
        float w = 1.f + 5.f * fabsf(box - t);
        a_w += w;
        a_i += p * t * w;
        a_u += (p + t) * w;
        float fp = p - mean_p;
        float ft = t - mean_t;
        float efm = __fdividef(2.f * fp * ft + 1e-8f, fp * fp + ft * ft + 1e-8f);
        float q = 1.f + efm;
        a_q += q * q * 0.25f;
        if (i < 31) vsum += sH[i + 31][tid] - sH[i][tid];
    }

    #pragma unroll
    for (int o = 16; o > 0; o >>= 1) {
        a_w += __shfl_xor_sync(~0u, a_w, o);
        a_i += __shfl_xor_sync(~0u, a_i, o);
        a_u += __shfl_xor_sync(~0u, a_u, o);
        a_q += __shfl_xor_sync(~0u, a_q, o);
    }
    if (lane == 0) { red[0][warp] = a_w; red[1][warp] = a_i; red[2][warp] = a_u; red[3][warp] = a_q; }
    __syncthreads();
    if (tid == 0) {
        float rw = 0.f, ri = 0.f, ru = 0.f, rq = 0.f;
        #pragma unroll
        for (int w = 0; w < 4; w++) { rw += red[0][w]; ri += red[1][w]; ru += red[2][w]; rq += red[3][w]; }
        atomicAdd(&g_wsum[b],  rw);
        atomicAdd(&g_inter[b], ri);
        atomicAdd(&g_uni[b],   ru);
        atomicAdd(&g_qsum[b],  rq);
        __threadfence();
        s_last = (atomicAdd(&g_done, 1) == gridDim.x - 1);
    }
    __syncthreads();

    if (s_last) {
        const int ib = tid;   // threads 0..31 handle one image each
        float v = 0.f;
        if (ib < B) {
            float bce = atomicAdd(&g_bce, 0.f) * (1.f / (float)NTOT);
            float ws  = atomicAdd(&g_wsum[ib],  0.f);
            float in_ = atomicAdd(&g_inter[ib], 0.f);
            float un_ = atomicAdd(&g_uni[ib],   0.f);
            float qs  = atomicAdd(&g_qsum[ib],  0.f);
            float wbce = (ws * bce + 1e-8f) / (ws + 1e-8f);
            float wiou = 1.f - (in_ + 1.f + 1e-8f) / (un_ - in_ + 1.f + 1e-8f);
            float el   = 1.f - qs * (1.f / (float)NPIX);
            v = wbce + wiou + el;
        }
        #pragma unroll
        for (int o = 16; o > 0; o >>= 1) v += __shfl_xor_sync(~0u, v, o);
        if (ib == 0) out[0] = v * (1.f / (float)B);
        if (ib < B) {
            g_sum_t[ib] = 0.f; g_sum_p[ib] = 0.f;
            g_wsum[ib]  = 0.f; g_inter[ib] = 0.f;
            g_uni[ib]   = 0.f; g_qsum[ib]  = 0.f;
        }
        if (ib == 0) { g_bce = 0.f; g_done = 0; }
    }
}

extern "C" void kernel_launch(void* const* d_in, const int* in_sizes, int n_in,
                              void* d_out, int out_size) {
    const float* y_pred   = (const float*)d_in[0];
    const float* y_target = (const float*)d_in[1];
    float* out = (float*)d_out;

    k_passA<<<2048, 256>>>(y_pred, y_target);
    k_passB<<<2048, 128>>>(y_pred, y_target, out);
}

// round 12
// speedup vs baseline: 1.6316x; 1.0123x over previous
#include <cuda_runtime.h>
#include <cuda_bf16.h>
#include <math.h>

#define B 32
#define HH 512
#define WW 512
#define NPIX (HH*WW)          // 262144
#define NTOT (B*NPIX)         // 8388608
#define KRAD 15               // box radius

// swizzle: one pad float per 16 -> stride-16 access patterns become
// stride-17 (odd) -> conflict-free across 32 banks
#define SWZ(i) ((i) + ((i) >> 4))
#define SWW 544                // 512 + 32 pad floats per row

// Scratch: horizontal box sums of y_target, bf16. 16.75 MB.
__device__ __nv_bfloat16 g_Hb[NTOT];

// Accumulators (zero at module load; Pass-B tail restores zeros every call)
__device__ float g_sum_t[B];
__device__ float g_sum_p[B];
__device__ float g_wsum[B];
__device__ float g_inter[B];
__device__ float g_uni[B];
__device__ float g_qsum[B];
__device__ float g_bce;
__device__ int   g_done;

__device__ __forceinline__ float fsigmoid(float x) {
    return __fdividef(1.f, 1.f + __expf(-x));
}

// bf16 (raw u16 bits) -> fp32: single shift, no MUFU/F2F
__device__ __forceinline__ float bf16bits_to_f(unsigned short u) {
    return __uint_as_float(((unsigned int)u) << 16);
}

// -------- Pass A: horizontal box sums (bf16 out) + sum_t, sum_p, bce ---------
// 8 warps per block, one warp per row. 2048 blocks cover 16384 rows.
__global__ __launch_bounds__(256) void k_passA(const float* __restrict__ P,
                                               const float* __restrict__ T) {
    __shared__ float sIn[8][SWW];    // swizzled input staging
    __shared__ float red[3][8];

    const int warp = threadIdx.x >> 5;
    const int lane = threadIdx.x & 31;
    const int rowg = blockIdx.x * 8 + warp;          // global row 0..16383
    const int b    = blockIdx.x >> 6;                // 64 blocks per image

    const float4* t4 = (const float4*)(T + (size_t)rowg * WW);
    const float4* p4 = (const float4*)(P + (size_t)rowg * WW);

    float lsum_t = 0.f, lsum_p = 0.f, lbce = 0.f;
    #pragma unroll
    for (int i = 0; i < 4; i++) {
        float4 tv = t4[lane + 32*i];
        float4 pv = p4[lane + 32*i];
        const int c0 = 4*lane + 128*i;
        sIn[warp][SWZ(c0+0)] = tv.x;
        sIn[warp][SWZ(c0+1)] = tv.y;
        sIn[warp][SWZ(c0+2)] = tv.z;
        sIn[warp][SWZ(c0+3)] = tv.w;
        float ts[4] = {tv.x, tv.y, tv.z, tv.w};
        float xs[4] = {pv.x, pv.y, pv.z, pv.w};
        #pragma unroll
        for (int k = 0; k < 4; k++) {
            float t = ts[k], x = xs[k];
            float p = fsigmoid(x);
            lsum_t += t;
            lsum_p += p;
            float sabs = (x >= 0.f) ? p : (1.f - p);
            lbce += fmaxf(x, 0.f) - x * t - __logf(sabs);
        }
    }
    __syncwarp();

    // per-lane sliding window over 16 contiguous columns, conflict-free reads
    const int base = lane * 16;
    float h[16];
    float s = 0.f;
    #pragma unroll
    for (int kk = 0; kk < 31; kk++) {
        int k = base - KRAD + kk;
        if (k >= 0 && k < WW) s += sIn[warp][SWZ(k)];
    }
    h[0] = s;
    #pragma unroll
    for (int j = 1; j < 16; j++) {
        int ka = base + KRAD + j;
        int kr = base - KRAD - 1 + j;
        if (ka < WW) s += sIn[warp][SWZ(ka)];
        if (kr >= 0) s -= sIn[warp][SWZ(kr)];
        h[j] = s;
    }

    // pack 16 fp32 -> 16 bf16 (32B) and store coalesced (lane-contiguous)
    __align__(16) __nv_bfloat162 hb2[8];
    #pragma unroll
    for (int k = 0; k < 8; k++)
        hb2[k] = __floats2bfloat162_rn(h[2*k], h[2*k+1]);
    uint4* dst = (uint4*)(g_Hb + (size_t)rowg * WW + base);
    const uint4* src = (const uint4*)hb2;
    dst[0] = src[0];
    dst[1] = src[1];

    #pragma unroll
    for (int o = 16; o > 0; o >>= 1) {
        lsum_t += __shfl_xor_sync(~0u, lsum_t, o);
        lsum_p += __shfl_xor_sync(~0u, lsum_p, o);
        lbce   += __shfl_xor_sync(~0u, lbce,   o);
    }
    if (lane == 0) { red[0][warp] = lsum_t; red[1][warp] = lsum_p; red[2][warp] = lbce; }
    __syncthreads();
    if (threadIdx.x == 0) {
        float a = 0.f, c = 0.f, d = 0.f;
        #pragma unroll
        for (int w = 0; w < 8; w++) { a += red[0][w]; c += red[1][w]; d += red[2][w]; }
        atomicAdd(&g_sum_t[b], a);
        atomicAdd(&g_sum_p[b], c);
        atomicAdd(&g_bce, d);
    }
}

// -------- Pass B: vertical box via bf16 SMEM halo + sums + E -----------------
// grid 1024, REVERSED decode: bxr = 1023-bx; b = bxr>>5, band = (bxr>>2)&7
// (64 rows), strip = bxr&3 (128 cols). Halo 94 rows bf16 = 23.5 KB smem ->
// 9 blocks/SM. bf16->fp32 at use is a 16-bit shift (1 ALU op).
__global__ __launch_bounds__(128, 9) void k_passB(const float* __restrict__ P,
                                                  const float* __restrict__ T,
                                                  float* __restrict__ out) {
    __shared__ __align__(16) unsigned short sH[94][128];  // 23.5 KB raw bf16
    __shared__ float red[4][4];
    __shared__ int s_last;

    const int bxr   = 1023 - blockIdx.x;
    const int b     = bxr >> 5;
    const int band  = (bxr >> 2) & 7;
    const int strip = bxr & 3;
    const int tid   = threadIdx.x;
    const int warp  = tid >> 5, lane = tid & 31;
    const int gcol  = strip * 128 + tid;
    const int r0    = band * 64;

    const __nv_bfloat16* Hb = g_Hb + (size_t)b * NPIX;
    const float* Tb = T + (size_t)b * NPIX;
    const float* Pb = P + (size_t)b * NPIX;

    // Stage H rows [r0-15, r0+78] raw (uint2 = 4 bf16 per lane), no converts.
    #pragma unroll
    for (int j = warp; j < 94; j += 4) {
        int gr = r0 - KRAD + j;
        uint2 u = make_uint2(0u, 0u);
        if (gr >= 0 && gr < HH)
            u = ((const uint2*)(Hb + (size_t)gr * WW + strip * 128))[lane];
        ((uint2*)sH[j])[lane] = u;
    }
    __syncthreads();

    const float mean_p = g_sum_p[b] * (1.f / (float)NPIX);
    const float mean_t = g_sum_t[b] * (1.f / (float)NPIX);

    // init vertical window: smem rows 0..30 (global r0-15..r0+15)
    float acc0 = 0.f, acc1 = 0.f, acc2 = 0.f, acc3 = 0.f;
    #pragma unroll
    for (int j = 0; j < 31; j++) {
        float v = bf16bits_to_f(sH[j][tid]);
        if ((j & 3) == 0) acc0 += v;
        else if ((j & 3) == 1) acc1 += v;
        else if ((j & 3) == 2) acc2 += v;
        else acc3 += v;
    }
    float vsum = (acc0 + acc1) + (acc2 + acc3);

    float a_w = 0.f, a_i = 0.f, a_u = 0.f, a_q = 0.f;
    #pragma unroll 8
    for (int i = 0; i < 64; i++) {
        float box = vsum * (1.f / 961.f);
        float t = Tb[(size_t)(r0 + i) * WW + gcol];
        float x = Pb[(size_t)(r0 + i) * WW + gcol];
        float p = fsigmoid(x);
        float w = 1.f + 5.f * fabsf(box - t);
        a_w += w;
        a_i += p * t * w;
        a_u += (p + t) * w;
        float fp = p - mean_p;
        float ft = t - mean_t;
        float efm = __fdividef(2.f * fp * ft + 1e-8f, fp * fp + ft * ft + 1e-8f);
        float q = 1.f + efm;
        a_q += q * q * 0.25f;
        if (i < 63)
            vsum += bf16bits_to_f(sH[i + 31][tid]) - bf16bits_to_f(sH[i][tid]);
    }

    #pragma unroll
    for (int o = 16; o > 0; o >>= 1) {
        a_w += __shfl_xor_sync(~0u, a_w, o);
        a_i += __shfl_xor_sync(~0u, a_i, o);
        a_u += __shfl_xor_sync(~0u, a_u, o);
        a_q += __shfl_xor_sync(~0u, a_q, o);
    }
    if (lane == 0) { red[0][warp] = a_w; red[1][warp] = a_i; red[2][warp] = a_u; red[3][warp] = a_q; }
    __syncthreads();
    if (tid == 0) {
        float rw = 0.f, ri = 0.f, ru = 0.f, rq = 0.f;
        #pragma unroll
        for (int w = 0; w < 4; w++) { rw += red[0][w]; ri += red[1][w]; ru += red[2][w]; rq += red[3][w]; }
        atomicAdd(&g_wsum[b],  rw);
        atomicAdd(&g_inter[b], ri);
        atomicAdd(&g_uni[b],   ru);
        atomicAdd(&g_qsum[b],  rq);
        __threadfence();
        s_last = (atomicAdd(&g_done, 1) == gridDim.x - 1);
    }
    __syncthreads();

    if (s_last) {
        const int ib = tid;   // threads 0..31 handle one image each
        float v = 0.f;
        if (ib < B) {
            float bce = atomicAdd(&g_bce, 0.f) * (1.f / (float)NTOT);
            float ws  = atomicAdd(&g_wsum[ib],  0.f);
            float in_ = atomicAdd(&g_inter[ib], 0.f);
            float un_ = atomicAdd(&g_uni[ib],   0.f);
            float qs  = atomicAdd(&g_qsum[ib],  0.f);
            float wbce = (ws * bce + 1e-8f) / (ws + 1e-8f);
            float wiou = 1.f - (in_ + 1.f + 1e-8f) / (un_ - in_ + 1.f + 1e-8f);
            float el   = 1.f - qs * (1.f / (float)NPIX);
            v = wbce + wiou + el;
        }
        #pragma unroll
        for (int o = 16; o > 0; o >>= 1) v += __shfl_xor_sync(~0u, v, o);
        if (ib == 0) out[0] = v * (1.f / (float)B);
        if (ib < B) {
            g_sum_t[ib] = 0.f; g_sum_p[ib] = 0.f;
            g_wsum[ib]  = 0.f; g_inter[ib] = 0.f;
            g_uni[ib]   = 0.f; g_qsum[ib]  = 0.f;
        }
        if (ib == 0) { g_bce = 0.f; g_done = 0; }
    }
}

extern "C" void kernel_launch(void* const* d_in, const int* in_sizes, int n_in,
                              void* d_out, int out_size) {
    const float* y_pred   = (const float*)d_in[0];
    const float* y_target = (const float*)d_in[1];
    float* out = (float*)d_out;

    k_passA<<<2048, 256>>>(y_pred, y_target);
    k_passB<<<1024, 128>>>(y_pred, y_target, out);
}